// round 7
// baseline (speedup 1.0000x reference)
#include <cuda_runtime.h>

#define NQ  8
#define DIM 256
#define SQ2 0.70710678118654752f

__device__ float2 g_psi[DIM];

__device__ __constant__ unsigned char PI_[28] =
    {0,0,0,0,0,0,0,1,1,1,1,1,1,2,2,2,2,2,3,3,3,3,4,4,4,5,5,6};
__device__ __constant__ unsigned char PJ_[28] =
    {1,2,3,4,5,6,7,2,3,4,5,6,7,3,4,5,6,7,4,5,6,7,5,6,7,6,7,7};

__device__ __forceinline__ float2 cmul(float2 a, float2 b) {
    return make_float2(a.x * b.x - a.y * b.y, a.x * b.y + a.y * b.x);
}
__device__ __forceinline__ float2 cmad(float2 acc, float2 a, float2 b) {
    return make_float2(acc.x + a.x * b.x - a.y * b.y,
                       acc.y + a.x * b.y + a.y * b.x);
}

// Fetch partner amplitudes for XOR-mask m. Register part of the mask is a
// compile-time template parameter (no dynamic register indexing); lane part
// uses shfl.xor. Warp-uniform control flow throughout.
template<int RM>
__device__ __forceinline__ void fetch_rm(const float2* a, float2* p, int lm) {
#pragma unroll
    for (int r = 0; r < 8; r++) {
        float2 v = a[r ^ RM];
        if (lm) {
            v.x = __shfl_xor_sync(0xffffffffu, v.x, lm);
            v.y = __shfl_xor_sync(0xffffffffu, v.y, lm);
        }
        p[r] = v;
    }
}
__device__ __forceinline__ void fetch(const float2* a, float2* p, int m) {
    const int rm = m >> 5, lm = m & 31;
    switch (rm) {
        case 0: fetch_rm<0>(a, p, lm); break;
        case 1: fetch_rm<1>(a, p, lm); break;
        case 2: fetch_rm<2>(a, p, lm); break;
        case 3: fetch_rm<3>(a, p, lm); break;
        case 4: fetch_rm<4>(a, p, lm); break;
        case 5: fetch_rm<5>(a, p, lm); break;
        case 6: fetch_rm<6>(a, p, lm); break;
        default: fetch_rm<7>(a, p, lm); break;
    }
}

// ---------------------------------------------------------------------------
// Fully fused kernel. Setup in parallel (8 warps), chain in warp 0 with the
// state register-resident (zero barriers, zero smem traffic in the chain),
// outer product by all 8 warps.
// ---------------------------------------------------------------------------
__global__ void __launch_bounds__(256, 1)
fused_kernel(const float* __restrict__ x,
             const float* __restrict__ w,
             const float* __restrict__ cplg,
             float4* __restrict__ out,
             int write_out) {
    __shared__ float2 pairM[28][16];
    __shared__ float2 u1s[8][4];
    __shared__ float2 spsi[DIM];
    __shared__ float  sw[210];
    __shared__ float  scpl[64];
    __shared__ float  xn[DIM];
    __shared__ float  isc[28], iss[28];
    __shared__ float  red[8];
    __shared__ unsigned amask_sh;

    const int tid  = threadIdx.x;
    const int lane = tid & 31;
    const int wid  = tid >> 5;

    if (tid < 210) sw[tid]   = w[tid];
    if (tid < 64)  scpl[tid] = cplg[tid];
    const float xv = x[tid];
    float ss = xv * xv;
#pragma unroll
    for (int o = 16; o; o >>= 1) ss += __shfl_xor_sync(0xffffffffu, ss, o);
    if (lane == 0) red[wid] = ss;
    __syncthreads();                       // sw, scpl, red ready

    const float inv = rsqrtf(red[0] + red[1] + red[2] + red[3] +
                             red[4] + red[5] + red[6] + red[7]);
    xn[tid] = xv * inv;

    if (wid == 0) {
        // min/max over 64 coupling entries via warp reduction
        float mn = fminf(scpl[lane], scpl[lane + 32]);
        float mx = fmaxf(scpl[lane], scpl[lane + 32]);
#pragma unroll
        for (int o = 16; o; o >>= 1) {
            mn = fminf(mn, __shfl_xor_sync(0xffffffffu, mn, o));
            mx = fmaxf(mx, __shfl_xor_sync(0xffffffffu, mx, o));
        }
        const float range = mx - mn;
        bool bit = false;
        if (lane < 28)
            bit = (scpl[PI_[lane] * 8 + PJ_[lane]] - mn) / range > 0.5f;
        const unsigned am = __ballot_sync(0xffffffffu, bit);
        if (lane == 0) amask_sh = am;
    }
    __syncthreads();                       // amask, xn ready
    const unsigned amask = amask_sh;

    // ---- parallel coefficient build ----
    if (tid < 112) {
        // fused conv+pool 4x4: thread (p*4+col) builds one column
        const int p   = tid >> 2;
        const int col = tid & 3;
        const int widx = 3 * NQ + 6 * __popc(amask & ((1u << p) - 1u));

        float2 v0 = make_float2(col == 0 ? 1.f : 0.f, 0.f);
        float2 v1 = make_float2(col == 1 ? 1.f : 0.f, 0.f);
        float2 v2 = make_float2(col == 2 ? 1.f : 0.f, 0.f);
        float2 v3 = make_float2(col == 3 ? 1.f : 0.f, 0.f);

#define PHASE_I(er, ei) { const float2 e = make_float2(er, ei), ec = make_float2(er, -(ei)); \
        v0 = cmul(v0, e); v1 = cmul(v1, e); v2 = cmul(v2, ec); v3 = cmul(v3, ec); }
#define PHASE_J(er, ei) { const float2 e = make_float2(er, ei), ec = make_float2(er, -(ei)); \
        v0 = cmul(v0, e); v1 = cmul(v1, ec); v2 = cmul(v2, e); v3 = cmul(v3, ec); }
#define RY_J(c, s) { float2 t; \
        t  = make_float2((c)*v0.x - (s)*v1.x, (c)*v0.y - (s)*v1.y); \
        v1 = make_float2((s)*v0.x + (c)*v1.x, (s)*v0.y + (c)*v1.y); v0 = t; \
        t  = make_float2((c)*v2.x - (s)*v3.x, (c)*v2.y - (s)*v3.y); \
        v3 = make_float2((s)*v2.x + (c)*v3.x, (s)*v2.y + (c)*v3.y); v2 = t; }
#define SWAP13 { const float2 t = v1; v1 = v3; v3 = t; }
#define SWAP23 { const float2 t = v2; v2 = v3; v3 = t; }

        float s0, c0, s1, c1, s2, c2, s3, c3, s4, c4, s5, c5;
        __sincosf(0.5f * sw[widx + 0], &s0, &c0);
        __sincosf(0.5f * sw[widx + 1], &s1, &c1);
        __sincosf(0.5f * sw[widx + 2], &s2, &c2);
        __sincosf(0.5f * sw[widx + 3], &s3, &c3);
        __sincosf(0.5f * sw[widx + 4], &s4, &c4);
        __sincosf(0.5f * sw[widx + 5], &s5, &c5);

        PHASE_J(SQ2,  SQ2);
        SWAP13;
        PHASE_I(c0, -s0);
        RY_J(c1, s1);
        SWAP23;
        RY_J(c2, s2);
        SWAP13;
        PHASE_I(SQ2, -SQ2);
        PHASE_J(SQ2,  SQ2);
        SWAP13;
        PHASE_I(c3, -s3);
        RY_J(c4, s4);
        SWAP23;
        RY_J(c5, s5);

        pairM[p][0 * 4 + col] = v0;
        pairM[p][1 * 4 + col] = v1;
        pairM[p][2 * 4 + col] = v2;
        pairM[p][3 * 4 + col] = v3;
#undef PHASE_I
#undef PHASE_J
#undef RY_J
#undef SWAP13
#undef SWAP23
    } else if (tid >= 128 && tid < 136) {
        // fused single-qubit u = Rz*Ry*Rx for qubit q
        const int q = tid - 128;
        float sx, cx, sy, cy, sz, cz;
        __sincosf(0.5f * sw[q],      &sx, &cx);
        __sincosf(0.5f * sw[q + 8],  &sy, &cy);
        __sincosf(0.5f * sw[q + 16], &sz, &cz);
        const float2 A00 = make_float2(cy * cx,  sy * sx);
        const float2 A01 = make_float2(-sy * cx, -cy * sx);
        const float2 A10 = make_float2( sy * cx, -cy * sx);
        const float2 A11 = make_float2(cy * cx, -sy * sx);
        const float2 ez  = make_float2(cz, -sz);
        const float2 ezc = make_float2(cz,  sz);
        u1s[q][0] = cmul(ez,  A00);
        u1s[q][1] = cmul(ez,  A01);
        u1s[q][2] = cmul(ezc, A10);
        u1s[q][3] = cmul(ezc, A11);
    } else if (tid >= 160 && tid < 188) {
        const int p = tid - 160;
        float s, c;
        __sincosf(0.5f * scpl[PI_[p] * 8 + PJ_[p]], &s, &c);
        isc[p] = c; iss[p] = s;
    }
    __syncthreads();                       // all coefficients ready

    // ---- register-resident chain, warp 0 only, no barriers ----
    if (wid == 0) {
        float2 a[8], p[8], n[8];
#pragma unroll
        for (int r = 0; r < 8; r++)
            a[r] = make_float2(xn[(r << 5) | lane], 0.f);

        // single-qubit fused gates
#pragma unroll 1
        for (int q = 0; q < 8; q++) {
            const int b = 7 - q;
            const float2 u00 = u1s[q][0], u01 = u1s[q][1];
            const float2 u10 = u1s[q][2], u11 = u1s[q][3];
            fetch(a, p, 1 << b);
#pragma unroll
            for (int r = 0; r < 8; r++) {
                const int bit = (((r << 5) | lane) >> b) & 1;
                const float2 own = a[r], pv = p[r];
                a[r] = bit ? cmad(cmul(u10, pv), u11, own)
                           : cmad(cmul(u00, own), u01, pv);
            }
        }

        // ising_xx gates
#pragma unroll 1
        for (int pp = 0; pp < 28; pp++) {
            const int m = (1 << (7 - PI_[pp])) | (1 << (7 - PJ_[pp]));
            const float c = isc[pp], s = iss[pp];
            fetch(a, p, m);
#pragma unroll
            for (int r = 0; r < 8; r++)
                a[r] = make_float2(c * a[r].x + s * p[r].y,
                                   c * a[r].y - s * p[r].x);
        }

        // fused conv+pool 4x4 applies
#pragma unroll 1
        for (int pp = 0; pp < 28; pp++) {
            if (!((amask >> pp) & 1u)) continue;
            const int bi = 7 - PI_[pp], bj = 7 - PJ_[pp];
            const int mi = 1 << bi, mj = 1 << bj;
            const float2* M = &pairM[pp][0];
            // columns: own -> row, ^mj -> row^1, ^mi -> row^2, ^both -> row^3
            fetch(a, p, mj);
#pragma unroll
            for (int r = 0; r < 8; r++) {
                const int idx = (r << 5) | lane;
                const int row = (((idx >> bi) & 1) << 1) | ((idx >> bj) & 1);
                n[r] = cmad(cmul(M[row * 4 + row], a[r]),
                            M[row * 4 + (row ^ 1)], p[r]);
            }
            fetch(a, p, mi);
#pragma unroll
            for (int r = 0; r < 8; r++) {
                const int idx = (r << 5) | lane;
                const int row = (((idx >> bi) & 1) << 1) | ((idx >> bj) & 1);
                n[r] = cmad(n[r], M[row * 4 + (row ^ 2)], p[r]);
            }
            fetch(a, p, mi | mj);
#pragma unroll
            for (int r = 0; r < 8; r++) {
                const int idx = (r << 5) | lane;
                const int row = (((idx >> bi) & 1) << 1) | ((idx >> bj) & 1);
                a[r] = cmad(n[r], M[row * 4 + (row ^ 3)], p[r]);
            }
        }

        // publish final state
#pragma unroll
        for (int r = 0; r < 8; r++) {
            const int idx = (r << 5) | lane;
            spsi[idx]  = a[r];
            g_psi[idx] = a[r];
        }
    }
    __syncthreads();

    if (!write_out) return;

    // ---- outer product (real part), all 8 warps ----
    const int q  = tid & 63;
    const int c0 = q << 2;
    const float2 b0 = spsi[c0];
    const float2 b1 = spsi[c0 + 1];
    const float2 b2 = spsi[c0 + 2];
    const float2 b3 = spsi[c0 + 3];
    const int rsub = tid >> 6;
#pragma unroll 4
    for (int it = 0; it < 64; it++) {
        const int r = (it << 2) | rsub;
        const float2 av = spsi[r];
        float4 o;
        o.x = av.x * b0.x + av.y * b0.y;
        o.y = av.x * b1.x + av.y * b1.y;
        o.z = av.x * b2.x + av.y * b2.y;
        o.w = av.x * b3.x + av.y * b3.y;
        out[(r << 6) + q] = o;
    }
}

// fallback for unexpected out_size (planar [Re|Im])
__global__ void __launch_bounds__(256)
outer_planar_kernel(float* __restrict__ out) {
    const int r = blockIdx.x;
    const int c = threadIdx.x;
    const float2 a = g_psi[r];
    const float2 b = g_psi[c];
    out[r * DIM + c]             = a.x * b.x + a.y * b.y;
    out[DIM * DIM + r * DIM + c] = a.y * b.x - a.x * b.y;
}

extern "C" void kernel_launch(void* const* d_in, const int* in_sizes, int n_in,
                              void* d_out, int out_size) {
    const float* x   = nullptr;
    const float* w   = nullptr;
    const float* cpl = nullptr;
    for (int i = 0; i < n_in; i++) {
        if      (in_sizes[i] == 256) x   = (const float*)d_in[i];
        else if (in_sizes[i] == 210) w   = (const float*)d_in[i];
        else if (in_sizes[i] == 64)  cpl = (const float*)d_in[i];
    }

    const int real_only = (out_size == DIM * DIM);
    fused_kernel<<<1, 256>>>(x, w, cpl, (float4*)d_out, real_only);
    if (!real_only) {
        outer_planar_kernel<<<DIM, DIM>>>((float*)d_out);
    }
}

// round 8
// speedup vs baseline: 1.7924x; 1.7924x over previous
#include <cuda_runtime.h>

#define NQ  8
#define DIM 256
#define SQ2 0.70710678118654752f

__device__ float2 g_psi[DIM];

__device__ __constant__ unsigned char PI_[28] =
    {0,0,0,0,0,0,0,1,1,1,1,1,1,2,2,2,2,2,3,3,3,3,4,4,4,5,5,6};
__device__ __constant__ unsigned char PJ_[28] =
    {1,2,3,4,5,6,7,2,3,4,5,6,7,3,4,5,6,7,4,5,6,7,5,6,7,6,7,7};

// ising fusion groups: pairs (i,j1) and (i,j2); j2==255 -> single pair
__device__ __constant__ unsigned char GI_[16]  = {0,0,0,0,1,1,1,2,2,2,3,3,4,4,5,6};
__device__ __constant__ unsigned char GJ1_[16] = {1,3,5,7,2,4,6,3,5,7,4,6,5,7,6,7};
__device__ __constant__ unsigned char GJ2_[16] = {2,4,6,255,3,5,7,4,6,255,5,7,6,255,7,255};

__device__ __forceinline__ float2 cmul(float2 a, float2 b) {
    return make_float2(a.x * b.x - a.y * b.y, a.x * b.y + a.y * b.x);
}
__device__ __forceinline__ float2 cmad(float2 acc, float2 a, float2 b) {
    return make_float2(acc.x + a.x * b.x - a.y * b.y,
                       acc.y + a.x * b.y + a.y * b.x);
}

// ---------------------------------------------------------------------------
// One fused kernel: parallel coefficient setup -> 256-thread barrier chain
// (thin steps, all trig precomputed) -> outer product by all warps.
// ---------------------------------------------------------------------------
__global__ void __launch_bounds__(256, 1)
fused_kernel(const float* __restrict__ x,
             const float* __restrict__ w,
             const float* __restrict__ cplg,
             float4* __restrict__ out,
             int write_out) {
    __shared__ float2 buf[2][DIM];      // ping-pong state
    __shared__ float2 pairM[28][16];    // fused conv+pool 4x4 per pair
    __shared__ float2 u2s[4][16];       // paired single-qubit 4x4 per group
    __shared__ float2 u1s[8][4];        // per-qubit fused 2x2
    __shared__ float  gcc[16], gsc[16], gcs[16], gss[16];  // ising group coeffs
    __shared__ float  sw[210];
    __shared__ float  scpl[64];
    __shared__ float  red[8];
    __shared__ unsigned amask_sh;

    const int tid  = threadIdx.x;
    const int lane = tid & 31;
    const int wid  = tid >> 5;

    if (tid < 210) sw[tid]   = w[tid];
    if (tid < 64)  scpl[tid] = cplg[tid];
    const float xv = x[tid];
    float ssum = xv * xv;
#pragma unroll
    for (int o = 16; o; o >>= 1) ssum += __shfl_xor_sync(0xffffffffu, ssum, o);
    if (lane == 0) red[wid] = ssum;
    __syncthreads();                                  // sync0: sw, scpl, red

    // ---------------- phase 1 (parallel) ----------------
    const float inv = rsqrtf(red[0] + red[1] + red[2] + red[3] +
                             red[4] + red[5] + red[6] + red[7]);
    buf[0][tid] = make_float2(xv * inv, 0.f);

    if (wid == 0) {
        // adjacency mask via warp reduction + ballot
        float mn = fminf(scpl[lane], scpl[lane + 32]);
        float mx = fmaxf(scpl[lane], scpl[lane + 32]);
#pragma unroll
        for (int o = 16; o; o >>= 1) {
            mn = fminf(mn, __shfl_xor_sync(0xffffffffu, mn, o));
            mx = fmaxf(mx, __shfl_xor_sync(0xffffffffu, mx, o));
        }
        const float range = mx - mn;
        bool bit = false;
        if (lane < 28)
            bit = (scpl[PI_[lane] * 8 + PJ_[lane]] - mn) / range > 0.5f;
        const unsigned am = __ballot_sync(0xffffffffu, bit);
        if (lane == 0) amask_sh = am;
    } else if (tid >= 128 && tid < 136) {
        // fused single-qubit u = Rz*Ry*Rx for qubit q
        const int q = tid - 128;
        float sx, cx, sy, cy, sz, cz;
        __sincosf(0.5f * sw[q],      &sx, &cx);
        __sincosf(0.5f * sw[q + 8],  &sy, &cy);
        __sincosf(0.5f * sw[q + 16], &sz, &cz);
        // Ry*Rx entries
        const float2 A00 = make_float2(cy * cx,  sy * sx);
        const float2 A01 = make_float2(-sy * cx, -cy * sx);
        const float2 A10 = make_float2( sy * cx, -cy * sx);
        const float2 A11 = make_float2(cy * cx, -sy * sx);
        const float2 ez  = make_float2(cz, -sz);
        const float2 ezc = make_float2(cz,  sz);
        u1s[q][0] = cmul(ez,  A00);
        u1s[q][1] = cmul(ez,  A01);
        u1s[q][2] = cmul(ezc, A10);
        u1s[q][3] = cmul(ezc, A11);
    } else if (tid >= 160 && tid < 176) {
        // ising group coefficients
        const int t = tid - 160;
        const int i = GI_[t], j1 = GJ1_[t], j2 = GJ2_[t];
        float s1, c1, s2, c2;
        __sincosf(0.5f * scpl[i * 8 + j1], &s1, &c1);
        if (j2 == 255) { s2 = 0.f; c2 = 1.f; }
        else           __sincosf(0.5f * scpl[i * 8 + j2], &s2, &c2);
        gcc[t] = c1 * c2;
        gsc[t] = s1 * c2;
        gcs[t] = c1 * s2;
        gss[t] = s1 * s2;
    }
    __syncthreads();                                  // sync1: amask, u1s
    const unsigned amask = amask_sh;

    // ---------------- phase 2 (parallel) ----------------
    if (tid < 112) {
        // fused conv+pool 4x4: thread (p*4+col) builds one column
        const int p   = tid >> 2;
        const int col = tid & 3;
        const int widx = 3 * NQ + 6 * __popc(amask & ((1u << p) - 1u));

        float2 v0 = make_float2(col == 0 ? 1.f : 0.f, 0.f);
        float2 v1 = make_float2(col == 1 ? 1.f : 0.f, 0.f);
        float2 v2 = make_float2(col == 2 ? 1.f : 0.f, 0.f);
        float2 v3 = make_float2(col == 3 ? 1.f : 0.f, 0.f);

#define PHASE_I(er, ei) { const float2 e = make_float2(er, ei), ec = make_float2(er, -(ei)); \
        v0 = cmul(v0, e); v1 = cmul(v1, e); v2 = cmul(v2, ec); v3 = cmul(v3, ec); }
#define PHASE_J(er, ei) { const float2 e = make_float2(er, ei), ec = make_float2(er, -(ei)); \
        v0 = cmul(v0, e); v1 = cmul(v1, ec); v2 = cmul(v2, e); v3 = cmul(v3, ec); }
#define RY_J(c, s) { float2 t; \
        t  = make_float2((c)*v0.x - (s)*v1.x, (c)*v0.y - (s)*v1.y); \
        v1 = make_float2((s)*v0.x + (c)*v1.x, (s)*v0.y + (c)*v1.y); v0 = t; \
        t  = make_float2((c)*v2.x - (s)*v3.x, (c)*v2.y - (s)*v3.y); \
        v3 = make_float2((s)*v2.x + (c)*v3.x, (s)*v2.y + (c)*v3.y); v2 = t; }
#define SWAP13 { const float2 t = v1; v1 = v3; v3 = t; }
#define SWAP23 { const float2 t = v2; v2 = v3; v3 = t; }

        float s0, c0, s1, c1, s2, c2, s3, c3, s4, c4, s5, c5;
        __sincosf(0.5f * sw[widx + 0], &s0, &c0);
        __sincosf(0.5f * sw[widx + 1], &s1, &c1);
        __sincosf(0.5f * sw[widx + 2], &s2, &c2);
        __sincosf(0.5f * sw[widx + 3], &s3, &c3);
        __sincosf(0.5f * sw[widx + 4], &s4, &c4);
        __sincosf(0.5f * sw[widx + 5], &s5, &c5);

        PHASE_J(SQ2,  SQ2);
        SWAP13;
        PHASE_I(c0, -s0);
        RY_J(c1, s1);
        SWAP23;
        RY_J(c2, s2);
        SWAP13;
        PHASE_I(SQ2, -SQ2);
        PHASE_J(SQ2,  SQ2);
        SWAP13;
        PHASE_I(c3, -s3);
        RY_J(c4, s4);
        SWAP23;
        RY_J(c5, s5);

        pairM[p][0 * 4 + col] = v0;
        pairM[p][1 * 4 + col] = v1;
        pairM[p][2 * 4 + col] = v2;
        pairM[p][3 * 4 + col] = v3;
#undef PHASE_I
#undef PHASE_J
#undef RY_J
#undef SWAP13
#undef SWAP23
    } else if (tid < 176) {
        // paired single-qubit 4x4: c[row][col] = ua[ra][ka] * ub[rb][kb]
        const int t   = tid - 112;
        const int g   = t >> 4;
        const int row = (t >> 2) & 3;
        const int col = t & 3;
        const int qa = 2 * g, qb = 2 * g + 1;
        const float2 ea = u1s[qa][(row >> 1) * 2 + (col >> 1)];
        const float2 eb = u1s[qb][(row & 1) * 2 + (col & 1)];
        u2s[g][row * 4 + col] = cmul(ea, eb);
    }
    __syncthreads();                                  // sync2: chain start

    // ---------------- barrier chain (thin steps) ----------------
    int cp = 0;

    // 4 paired single-qubit 4x4 steps
#pragma unroll 1
    for (int g = 0; g < 4; g++) {
        const int ba = 7 - 2 * g, bb = 6 - 2 * g;
        const int ma = 1 << ba, mb = 1 << bb;
        const int row  = (((tid >> ba) & 1) << 1) | ((tid >> bb) & 1);
        const int base = tid & ~(ma | mb);
        const float2* M = &u2s[g][row * 4];
        float2 r = cmul(M[0], buf[cp][base]);
        r = cmad(r, M[1], buf[cp][base | mb]);
        r = cmad(r, M[2], buf[cp][base | ma]);
        r = cmad(r, M[3], buf[cp][base | ma | mb]);
        buf[cp ^ 1][tid] = r;
        __syncthreads();
        cp ^= 1;
    }

    // 16 fused ising steps (uniform coefficients, no row indexing)
#pragma unroll 1
    for (int t = 0; t < 16; t++) {
        const int i = GI_[t], j1 = GJ1_[t], j2 = GJ2_[t];
        const int m1 = (1 << (7 - i)) | (1 << (7 - j1));
        const int m2 = (j2 == 255) ? m1 : ((1 << (7 - i)) | (1 << (7 - j2)));
        const float cc = gcc[t], sc = gsc[t], cs = gcs[t], ss = gss[t];
        const float2 A = buf[cp][tid];
        const float2 B = buf[cp][tid ^ m1];
        const float2 C = buf[cp][tid ^ m2];
        const float2 D = buf[cp][tid ^ m1 ^ m2];
        buf[cp ^ 1][tid] = make_float2(
            cc * A.x + sc * B.y + cs * C.y - ss * D.x,
            cc * A.y - sc * B.x - cs * C.x - ss * D.y);
        __syncthreads();
        cp ^= 1;
    }

    // fused conv+pool 4x4 applies on active pairs
#pragma unroll 1
    for (int p = 0; p < 28; p++) {
        if (!((amask >> p) & 1u)) continue;
        const int bi = 7 - PI_[p], bj = 7 - PJ_[p];
        const int mi = 1 << bi, mj = 1 << bj;
        const int row  = (((tid >> bi) & 1) << 1) | ((tid >> bj) & 1);
        const int base = tid & ~(mi | mj);
        const float2* M = &pairM[p][row * 4];
        float2 r = cmul(M[0], buf[cp][base]);
        r = cmad(r, M[1], buf[cp][base | mj]);
        r = cmad(r, M[2], buf[cp][base | mi]);
        r = cmad(r, M[3], buf[cp][base | mi | mj]);
        buf[cp ^ 1][tid] = r;
        __syncthreads();
        cp ^= 1;
    }

    g_psi[tid] = buf[cp][tid];

    if (!write_out) return;

    // ---------------- outer product (real part) ----------------
    const float2* ps = buf[cp];
    const int q  = tid & 63;
    const int c0 = q << 2;
    const float2 b0 = ps[c0];
    const float2 b1 = ps[c0 + 1];
    const float2 b2 = ps[c0 + 2];
    const float2 b3 = ps[c0 + 3];
    const int rsub = tid >> 6;
#pragma unroll 4
    for (int it = 0; it < 64; it++) {
        const int r = (it << 2) | rsub;
        const float2 av = ps[r];
        float4 o;
        o.x = av.x * b0.x + av.y * b0.y;
        o.y = av.x * b1.x + av.y * b1.y;
        o.z = av.x * b2.x + av.y * b2.y;
        o.w = av.x * b3.x + av.y * b3.y;
        out[(r << 6) + q] = o;
    }
}

// fallback for unexpected out_size (planar [Re|Im])
__global__ void __launch_bounds__(256)
outer_planar_kernel(float* __restrict__ out) {
    const int r = blockIdx.x;
    const int c = threadIdx.x;
    const float2 a = g_psi[r];
    const float2 b = g_psi[c];
    out[r * DIM + c]             = a.x * b.x + a.y * b.y;
    out[DIM * DIM + r * DIM + c] = a.y * b.x - a.x * b.y;
}

extern "C" void kernel_launch(void* const* d_in, const int* in_sizes, int n_in,
                              void* d_out, int out_size) {
    const float* x   = nullptr;
    const float* w   = nullptr;
    const float* cpl = nullptr;
    for (int i = 0; i < n_in; i++) {
        if      (in_sizes[i] == 256) x   = (const float*)d_in[i];
        else if (in_sizes[i] == 210) w   = (const float*)d_in[i];
        else if (in_sizes[i] == 64)  cpl = (const float*)d_in[i];
    }

    const int real_only = (out_size == DIM * DIM);
    fused_kernel<<<1, 256>>>(x, w, cpl, (float4*)d_out, real_only);
    if (!real_only) {
        outer_planar_kernel<<<DIM, DIM>>>((float*)d_out);
    }
}

// round 9
// speedup vs baseline: 1.8077x; 1.0085x over previous
#include <cuda_runtime.h>

#define NQ  8
#define DIM 256
#define SQ2 0.70710678118654752f

__device__ float2 g_psi[DIM];

__device__ __constant__ unsigned char PI_[28] =
    {0,0,0,0,0,0,0,1,1,1,1,1,1,2,2,2,2,2,3,3,3,3,4,4,4,5,5,6};
__device__ __constant__ unsigned char PJ_[28] =
    {1,2,3,4,5,6,7,2,3,4,5,6,7,3,4,5,6,7,4,5,6,7,5,6,7,6,7,7};

__device__ __forceinline__ float2 cmul(float2 a, float2 b) {
    return make_float2(a.x * b.x - a.y * b.y, a.x * b.y + a.y * b.x);
}
__device__ __forceinline__ float2 cmad(float2 acc, float2 a, float2 b) {
    return make_float2(acc.x + a.x * b.x - a.y * b.y,
                       acc.y + a.x * b.y + a.y * b.x);
}

// ---------------------------------------------------------------------------
// One fused kernel.  Chain = 4 paired-1q steps (H-folded, D folded into the
// last write) + 4 H-pair steps + dense conv/pool steps.
// ---------------------------------------------------------------------------
__global__ void __launch_bounds__(256, 1)
fused_kernel(const float* __restrict__ x,
             const float* __restrict__ w,
             const float* __restrict__ cplg,
             float4* __restrict__ out,
             int write_out) {
    __shared__ float2 buf[2][DIM];
    __shared__ float2 pairM[28][16];
    __shared__ float2 u2s[4][16];
    __shared__ float2 u1s[8][4];     // H * (Rz Ry Rx), per qubit
    __shared__ float2 sD[DIM];       // diagonal ising phases
    __shared__ float  sw[210];
    __shared__ float  scpl[64];
    __shared__ float  red[8];
    __shared__ int    actL[28];
    __shared__ int    actN_sh;
    __shared__ unsigned amask_sh;

    const int tid  = threadIdx.x;
    const int lane = tid & 31;
    const int wid  = tid >> 5;

    if (tid < 210) sw[tid]   = w[tid];
    if (tid < 64)  scpl[tid] = cplg[tid];
    const float xv = x[tid];
    float ssum = xv * xv;
#pragma unroll
    for (int o = 16; o; o >>= 1) ssum += __shfl_xor_sync(0xffffffffu, ssum, o);
    if (lane == 0) red[wid] = ssum;
    __syncthreads();                               // sync0

    // ---------------- phase 1 ----------------
    const float inv = rsqrtf(red[0] + red[1] + red[2] + red[3] +
                             red[4] + red[5] + red[6] + red[7]);
    buf[0][tid] = make_float2(xv * inv, 0.f);

    // per-thread diagonal phase: theta = sum_p  +-phi_p/2  (+ if bits equal)
    {
        float th = 0.f;
#pragma unroll
        for (int p = 0; p < 28; p++) {
            const int i = PI_[p], j = PJ_[p];
            const float phi = scpl[i * 8 + j];
            const int b = ((tid >> (7 - i)) ^ (tid >> (7 - j))) & 1;
            th += b ? -0.5f * phi : 0.5f * phi;
        }
        float s, c;
        __sincosf(th, &s, &c);
        sD[tid] = make_float2(c, -s);
    }

    if (wid == 0) {
        float mn = fminf(scpl[lane], scpl[lane + 32]);
        float mx = fmaxf(scpl[lane], scpl[lane + 32]);
#pragma unroll
        for (int o = 16; o; o >>= 1) {
            mn = fminf(mn, __shfl_xor_sync(0xffffffffu, mn, o));
            mx = fmaxf(mx, __shfl_xor_sync(0xffffffffu, mx, o));
        }
        const float range = mx - mn;
        bool bit = false;
        if (lane < 28)
            bit = (scpl[PI_[lane] * 8 + PJ_[lane]] - mn) / range > 0.5f;
        const unsigned am = __ballot_sync(0xffffffffu, bit);
        if (lane == 0) amask_sh = am;
    } else if (tid >= 128 && tid < 136) {
        // u' = H * Rz*Ry*Rx for qubit q
        const int q = tid - 128;
        float sx, cx, sy, cy, sz, cz;
        __sincosf(0.5f * sw[q],      &sx, &cx);
        __sincosf(0.5f * sw[q + 8],  &sy, &cy);
        __sincosf(0.5f * sw[q + 16], &sz, &cz);
        const float2 A00 = make_float2(cy * cx,  sy * sx);
        const float2 A01 = make_float2(-sy * cx, -cy * sx);
        const float2 A10 = make_float2( sy * cx, -cy * sx);
        const float2 A11 = make_float2(cy * cx, -sy * sx);
        const float2 ez  = make_float2(cz, -sz);
        const float2 ezc = make_float2(cz,  sz);
        const float2 u00 = cmul(ez,  A00);
        const float2 u01 = cmul(ez,  A01);
        const float2 u10 = cmul(ezc, A10);
        const float2 u11 = cmul(ezc, A11);
        // H*u, H = (1/sqrt2)[[1,1],[1,-1]]
        u1s[q][0] = make_float2(SQ2 * (u00.x + u10.x), SQ2 * (u00.y + u10.y));
        u1s[q][1] = make_float2(SQ2 * (u01.x + u11.x), SQ2 * (u01.y + u11.y));
        u1s[q][2] = make_float2(SQ2 * (u00.x - u10.x), SQ2 * (u00.y - u10.y));
        u1s[q][3] = make_float2(SQ2 * (u01.x - u11.x), SQ2 * (u01.y - u11.y));
    }
    __syncthreads();                               // sync1: amask, u1s, sD
    const unsigned amask = amask_sh;

    // ---------------- phase 2 ----------------
    if (tid < 112) {
        const int p   = tid >> 2;
        const int col = tid & 3;
        const int widx = 3 * NQ + 6 * __popc(amask & ((1u << p) - 1u));

        float2 v0 = make_float2(col == 0 ? 1.f : 0.f, 0.f);
        float2 v1 = make_float2(col == 1 ? 1.f : 0.f, 0.f);
        float2 v2 = make_float2(col == 2 ? 1.f : 0.f, 0.f);
        float2 v3 = make_float2(col == 3 ? 1.f : 0.f, 0.f);

#define PHASE_I(er, ei) { const float2 e = make_float2(er, ei), ec = make_float2(er, -(ei)); \
        v0 = cmul(v0, e); v1 = cmul(v1, e); v2 = cmul(v2, ec); v3 = cmul(v3, ec); }
#define PHASE_J(er, ei) { const float2 e = make_float2(er, ei), ec = make_float2(er, -(ei)); \
        v0 = cmul(v0, e); v1 = cmul(v1, ec); v2 = cmul(v2, e); v3 = cmul(v3, ec); }
#define RY_J(c, s) { float2 t; \
        t  = make_float2((c)*v0.x - (s)*v1.x, (c)*v0.y - (s)*v1.y); \
        v1 = make_float2((s)*v0.x + (c)*v1.x, (s)*v0.y + (c)*v1.y); v0 = t; \
        t  = make_float2((c)*v2.x - (s)*v3.x, (c)*v2.y - (s)*v3.y); \
        v3 = make_float2((s)*v2.x + (c)*v3.x, (s)*v2.y + (c)*v3.y); v2 = t; }
#define SWAP13 { const float2 t = v1; v1 = v3; v3 = t; }
#define SWAP23 { const float2 t = v2; v2 = v3; v3 = t; }

        float s0, c0, s1, c1, s2, c2, s3, c3, s4, c4, s5, c5;
        __sincosf(0.5f * sw[widx + 0], &s0, &c0);
        __sincosf(0.5f * sw[widx + 1], &s1, &c1);
        __sincosf(0.5f * sw[widx + 2], &s2, &c2);
        __sincosf(0.5f * sw[widx + 3], &s3, &c3);
        __sincosf(0.5f * sw[widx + 4], &s4, &c4);
        __sincosf(0.5f * sw[widx + 5], &s5, &c5);

        PHASE_J(SQ2,  SQ2);
        SWAP13;
        PHASE_I(c0, -s0);
        RY_J(c1, s1);
        SWAP23;
        RY_J(c2, s2);
        SWAP13;
        PHASE_I(SQ2, -SQ2);
        PHASE_J(SQ2,  SQ2);
        SWAP13;
        PHASE_I(c3, -s3);
        RY_J(c4, s4);
        SWAP23;
        RY_J(c5, s5);

        pairM[p][0 * 4 + col] = v0;
        pairM[p][1 * 4 + col] = v1;
        pairM[p][2 * 4 + col] = v2;
        pairM[p][3 * 4 + col] = v3;
#undef PHASE_I
#undef PHASE_J
#undef RY_J
#undef SWAP13
#undef SWAP23
    } else if (tid < 176) {
        const int t   = tid - 112;
        const int g   = t >> 4;
        const int row = (t >> 2) & 3;
        const int col = t & 3;
        const float2 ea = u1s[2 * g][(row >> 1) * 2 + (col >> 1)];
        const float2 eb = u1s[2 * g + 1][(row & 1) * 2 + (col & 1)];
        u2s[g][row * 4 + col] = cmul(ea, eb);
    } else if (tid == 192) {
        // dense active list: packed = p | mi<<8 | mj<<16
        int n = 0;
#pragma unroll
        for (int p = 0; p < 28; p++) {
            if ((amask >> p) & 1u) {
                actL[n++] = p | ((1 << (7 - PI_[p])) << 8)
                              | ((1 << (7 - PJ_[p])) << 16);
            }
        }
        actN_sh = n;
    }
    __syncthreads();                               // sync2: chain start
    const int actN = actN_sh;

    int cp = 0;

    // ---- 3 paired single-qubit steps (H folded) ----
#pragma unroll 1
    for (int g = 0; g < 3; g++) {
        const int ba = 7 - 2 * g, bb = 6 - 2 * g;
        const int ma = 1 << ba, mb = 1 << bb;
        const int row  = (((tid >> ba) & 1) << 1) | ((tid >> bb) & 1);
        const int base = tid & ~(ma | mb);
        const float2* M = &u2s[g][row * 4];
        float2 r = cmul(M[0], buf[cp][base]);
        r = cmad(r, M[1], buf[cp][base | mb]);
        r = cmad(r, M[2], buf[cp][base | ma]);
        r = cmad(r, M[3], buf[cp][base | ma | mb]);
        buf[cp ^ 1][tid] = r;
        __syncthreads();
        cp ^= 1;
    }
    // ---- 4th paired step, with ising diagonal D folded into the write ----
    {
        const int ba = 1, bb = 0;
        const int ma = 2, mb = 1;
        const int row  = (tid & 3);
        const int base = tid & ~3;
        const float2* M = &u2s[3][row * 4];
        float2 r = cmul(M[0], buf[cp][base]);
        r = cmad(r, M[1], buf[cp][base | mb]);
        r = cmad(r, M[2], buf[cp][base | ma]);
        r = cmad(r, M[3], buf[cp][base | ma | mb]);
        buf[cp ^ 1][tid] = cmul(sD[tid], r);
        __syncthreads();
        cp ^= 1;
    }

    // ---- 4 H(x)H steps (signs only) ----
#pragma unroll 1
    for (int g = 0; g < 4; g++) {
        const int ba = 7 - 2 * g, bb = 6 - 2 * g;
        const int ma = 1 << ba, mb = 1 << bb;
        const int base = tid & ~(ma | mb);
        const float sa = (tid & ma) ? -1.f : 1.f;
        const float sb = (tid & mb) ? -1.f : 1.f;
        const float2 a00 = buf[cp][base];
        const float2 a01 = buf[cp][base | mb];
        const float2 a10 = buf[cp][base | ma];
        const float2 a11 = buf[cp][base | ma | mb];
        float2 r;
        r.x = 0.5f * ((a00.x + sb * a01.x) + sa * (a10.x + sb * a11.x));
        r.y = 0.5f * ((a00.y + sb * a01.y) + sa * (a10.y + sb * a11.y));
        buf[cp ^ 1][tid] = r;
        __syncthreads();
        cp ^= 1;
    }

    // ---- dense conv+pool 4x4 applies ----
#pragma unroll 1
    for (int a = 0; a < actN; a++) {
        const int packed = actL[a];
        const int p  = packed & 255;
        const int mi = (packed >> 8) & 255;
        const int mj = (packed >> 16) & 255;
        const int row  = ((tid & mi) ? 2 : 0) | ((tid & mj) ? 1 : 0);
        const int base = tid & ~(mi | mj);
        const float2* M = &pairM[p][row * 4];
        float2 r = cmul(M[0], buf[cp][base]);
        r = cmad(r, M[1], buf[cp][base | mj]);
        r = cmad(r, M[2], buf[cp][base | mi]);
        r = cmad(r, M[3], buf[cp][base | mi | mj]);
        buf[cp ^ 1][tid] = r;
        __syncthreads();
        cp ^= 1;
    }

    g_psi[tid] = buf[cp][tid];

    if (!write_out) return;

    // ---- outer product (real part) ----
    const float2* ps = buf[cp];
    const int q  = tid & 63;
    const int c0 = q << 2;
    const float2 b0 = ps[c0];
    const float2 b1 = ps[c0 + 1];
    const float2 b2 = ps[c0 + 2];
    const float2 b3 = ps[c0 + 3];
    const int rsub = tid >> 6;
#pragma unroll 4
    for (int it = 0; it < 64; it++) {
        const int r = (it << 2) | rsub;
        const float2 av = ps[r];
        float4 o;
        o.x = av.x * b0.x + av.y * b0.y;
        o.y = av.x * b1.x + av.y * b1.y;
        o.z = av.x * b2.x + av.y * b2.y;
        o.w = av.x * b3.x + av.y * b3.y;
        out[(r << 6) + q] = o;
    }
}

// fallback for unexpected out_size (planar [Re|Im])
__global__ void __launch_bounds__(256)
outer_planar_kernel(float* __restrict__ out) {
    const int r = blockIdx.x;
    const int c = threadIdx.x;
    const float2 a = g_psi[r];
    const float2 b = g_psi[c];
    out[r * DIM + c]             = a.x * b.x + a.y * b.y;
    out[DIM * DIM + r * DIM + c] = a.y * b.x - a.x * b.y;
}

extern "C" void kernel_launch(void* const* d_in, const int* in_sizes, int n_in,
                              void* d_out, int out_size) {
    const float* x   = nullptr;
    const float* w   = nullptr;
    const float* cpl = nullptr;
    for (int i = 0; i < n_in; i++) {
        if      (in_sizes[i] == 256) x   = (const float*)d_in[i];
        else if (in_sizes[i] == 210) w   = (const float*)d_in[i];
        else if (in_sizes[i] == 64)  cpl = (const float*)d_in[i];
    }

    const int real_only = (out_size == DIM * DIM);
    fused_kernel<<<1, 256>>>(x, w, cpl, (float4*)d_out, real_only);
    if (!real_only) {
        outer_planar_kernel<<<DIM, DIM>>>((float*)d_out);
    }
}

// round 10
// speedup vs baseline: 2.1097x; 1.1671x over previous
#include <cuda_runtime.h>

#define NQ  8
#define DIM 256
#define SQ2 0.70710678118654752f

__device__ float2 g_psi[DIM];
__device__ volatile int g_flag;   // zero-initialized; reset by last worker
__device__ int g_done;            // zero-initialized; reset by last worker

__device__ __constant__ unsigned char PI_[28] =
    {0,0,0,0,0,0,0,1,1,1,1,1,1,2,2,2,2,2,3,3,3,3,4,4,4,5,5,6};
__device__ __constant__ unsigned char PJ_[28] =
    {1,2,3,4,5,6,7,2,3,4,5,6,7,3,4,5,6,7,4,5,6,7,5,6,7,6,7,7};

__device__ __forceinline__ float2 cmul(float2 a, float2 b) {
    return make_float2(a.x * b.x - a.y * b.y, a.x * b.y + a.y * b.x);
}
__device__ __forceinline__ float2 cmad(float2 acc, float2 a, float2 b) {
    return make_float2(acc.x + a.x * b.x - a.y * b.y,
                       acc.y + a.x * b.y + a.y * b.x);
}

// ---------------------------------------------------------------------------
// grid = 65: block 0 evolves the state; blocks 1..64 wait on a device flag
// and write the 256KB output in parallel (one float4 per thread).
// ---------------------------------------------------------------------------
__global__ void __launch_bounds__(256, 1)
fused_kernel(const float* __restrict__ x,
             const float* __restrict__ w,
             const float* __restrict__ cplg,
             float4* __restrict__ out) {
    const int tid = threadIdx.x;

    // ================= worker blocks: outer product =================
    if (blockIdx.x != 0) {
        __shared__ float2 ps[DIM];
        if (tid == 0) {
            while (g_flag == 0) {}
        }
        __syncthreads();
        __threadfence();
        ps[tid] = __ldcg(&g_psi[tid]);   // L2 load (bypass L1)
        __syncthreads();

        const int r = ((blockIdx.x - 1) << 2) | (tid >> 6);
        const int q = tid & 63;
        const float2 a  = ps[r];
        const float2 b0 = ps[(q << 2)];
        const float2 b1 = ps[(q << 2) + 1];
        const float2 b2 = ps[(q << 2) + 2];
        const float2 b3 = ps[(q << 2) + 3];
        float4 o;
        o.x = a.x * b0.x + a.y * b0.y;
        o.y = a.x * b1.x + a.y * b1.y;
        o.z = a.x * b2.x + a.y * b2.y;
        o.w = a.x * b3.x + a.y * b3.y;
        out[(r << 6) + q] = o;

        __syncthreads();
        if (tid == 0) {
            const int old = atomicAdd(&g_done, 1);
            if (old == 63) {            // last worker: reset for next replay
                g_done = 0;
                __threadfence();
                g_flag = 0;
            }
        }
        return;
    }

    // ================= block 0: evolution =================
    __shared__ float2 buf[2][DIM];
    __shared__ float2 pairM[28][16];
    __shared__ float2 u2s[4][16];
    __shared__ float2 u1s[8][4];     // H * (Rz Ry Rx), per qubit
    __shared__ float2 sD[DIM];       // diagonal ising phases
    __shared__ float  sw[210];
    __shared__ float  scpl[64];
    __shared__ float  red[8];
    __shared__ int    actL[28];
    __shared__ int    actN_sh;
    __shared__ unsigned amask_sh;

    const int lane = tid & 31;
    const int wid  = tid >> 5;

    if (tid < 210) sw[tid]   = w[tid];
    if (tid < 64)  scpl[tid] = cplg[tid];
    const float xv = x[tid];
    float ssum = xv * xv;
#pragma unroll
    for (int o = 16; o; o >>= 1) ssum += __shfl_xor_sync(0xffffffffu, ssum, o);
    if (lane == 0) red[wid] = ssum;
    __syncthreads();                               // sync0

    // ---------------- phase 1 ----------------
    const float inv = rsqrtf(red[0] + red[1] + red[2] + red[3] +
                             red[4] + red[5] + red[6] + red[7]);
    buf[0][tid] = make_float2(xv * inv, 0.f);

    // per-thread diagonal phase: theta = sum_p +-phi_p/2 (+ if bits equal)
    {
        float th = 0.f;
#pragma unroll
        for (int p = 0; p < 28; p++) {
            const int i = PI_[p], j = PJ_[p];
            const float phi = scpl[i * 8 + j];
            const int b = ((tid >> (7 - i)) ^ (tid >> (7 - j))) & 1;
            th += b ? -0.5f * phi : 0.5f * phi;
        }
        float s, c;
        __sincosf(th, &s, &c);
        sD[tid] = make_float2(c, -s);
    }

    if (wid == 0) {
        float mn = fminf(scpl[lane], scpl[lane + 32]);
        float mx = fmaxf(scpl[lane], scpl[lane + 32]);
#pragma unroll
        for (int o = 16; o; o >>= 1) {
            mn = fminf(mn, __shfl_xor_sync(0xffffffffu, mn, o));
            mx = fmaxf(mx, __shfl_xor_sync(0xffffffffu, mx, o));
        }
        const float range = mx - mn;
        bool bit = false;
        if (lane < 28)
            bit = (scpl[PI_[lane] * 8 + PJ_[lane]] - mn) / range > 0.5f;
        const unsigned am = __ballot_sync(0xffffffffu, bit);
        if (lane == 0) amask_sh = am;
    } else if (tid >= 128 && tid < 136) {
        // u' = H * Rz*Ry*Rx for qubit q
        const int q = tid - 128;
        float sx, cx, sy, cy, sz, cz;
        __sincosf(0.5f * sw[q],      &sx, &cx);
        __sincosf(0.5f * sw[q + 8],  &sy, &cy);
        __sincosf(0.5f * sw[q + 16], &sz, &cz);
        const float2 A00 = make_float2(cy * cx,  sy * sx);
        const float2 A01 = make_float2(-sy * cx, -cy * sx);
        const float2 A10 = make_float2( sy * cx, -cy * sx);
        const float2 A11 = make_float2(cy * cx, -sy * sx);
        const float2 ez  = make_float2(cz, -sz);
        const float2 ezc = make_float2(cz,  sz);
        const float2 u00 = cmul(ez,  A00);
        const float2 u01 = cmul(ez,  A01);
        const float2 u10 = cmul(ezc, A10);
        const float2 u11 = cmul(ezc, A11);
        u1s[q][0] = make_float2(SQ2 * (u00.x + u10.x), SQ2 * (u00.y + u10.y));
        u1s[q][1] = make_float2(SQ2 * (u01.x + u11.x), SQ2 * (u01.y + u11.y));
        u1s[q][2] = make_float2(SQ2 * (u00.x - u10.x), SQ2 * (u00.y - u10.y));
        u1s[q][3] = make_float2(SQ2 * (u01.x - u11.x), SQ2 * (u01.y - u11.y));
    }
    __syncthreads();                               // sync1: amask, u1s, sD
    const unsigned amask = amask_sh;

    // ---------------- phase 2 ----------------
    if (tid < 112) {
        const int p   = tid >> 2;
        const int col = tid & 3;
        const int widx = 3 * NQ + 6 * __popc(amask & ((1u << p) - 1u));

        float2 v0 = make_float2(col == 0 ? 1.f : 0.f, 0.f);
        float2 v1 = make_float2(col == 1 ? 1.f : 0.f, 0.f);
        float2 v2 = make_float2(col == 2 ? 1.f : 0.f, 0.f);
        float2 v3 = make_float2(col == 3 ? 1.f : 0.f, 0.f);

#define PHASE_I(er, ei) { const float2 e = make_float2(er, ei), ec = make_float2(er, -(ei)); \
        v0 = cmul(v0, e); v1 = cmul(v1, e); v2 = cmul(v2, ec); v3 = cmul(v3, ec); }
#define PHASE_J(er, ei) { const float2 e = make_float2(er, ei), ec = make_float2(er, -(ei)); \
        v0 = cmul(v0, e); v1 = cmul(v1, ec); v2 = cmul(v2, e); v3 = cmul(v3, ec); }
#define RY_J(c, s) { float2 t; \
        t  = make_float2((c)*v0.x - (s)*v1.x, (c)*v0.y - (s)*v1.y); \
        v1 = make_float2((s)*v0.x + (c)*v1.x, (s)*v0.y + (c)*v1.y); v0 = t; \
        t  = make_float2((c)*v2.x - (s)*v3.x, (c)*v2.y - (s)*v3.y); \
        v3 = make_float2((s)*v2.x + (c)*v3.x, (s)*v2.y + (c)*v3.y); v2 = t; }
#define SWAP13 { const float2 t = v1; v1 = v3; v3 = t; }
#define SWAP23 { const float2 t = v2; v2 = v3; v3 = t; }

        float s0, c0, s1, c1, s2, c2, s3, c3, s4, c4, s5, c5;
        __sincosf(0.5f * sw[widx + 0], &s0, &c0);
        __sincosf(0.5f * sw[widx + 1], &s1, &c1);
        __sincosf(0.5f * sw[widx + 2], &s2, &c2);
        __sincosf(0.5f * sw[widx + 3], &s3, &c3);
        __sincosf(0.5f * sw[widx + 4], &s4, &c4);
        __sincosf(0.5f * sw[widx + 5], &s5, &c5);

        PHASE_J(SQ2,  SQ2);
        SWAP13;
        PHASE_I(c0, -s0);
        RY_J(c1, s1);
        SWAP23;
        RY_J(c2, s2);
        SWAP13;
        PHASE_I(SQ2, -SQ2);
        PHASE_J(SQ2,  SQ2);
        SWAP13;
        PHASE_I(c3, -s3);
        RY_J(c4, s4);
        SWAP23;
        RY_J(c5, s5);

        pairM[p][0 * 4 + col] = v0;
        pairM[p][1 * 4 + col] = v1;
        pairM[p][2 * 4 + col] = v2;
        pairM[p][3 * 4 + col] = v3;
#undef PHASE_I
#undef PHASE_J
#undef RY_J
#undef SWAP13
#undef SWAP23
    } else if (tid < 176) {
        const int t   = tid - 112;
        const int g   = t >> 4;
        const int row = (t >> 2) & 3;
        const int col = t & 3;
        const float2 ea = u1s[2 * g][(row >> 1) * 2 + (col >> 1)];
        const float2 eb = u1s[2 * g + 1][(row & 1) * 2 + (col & 1)];
        u2s[g][row * 4 + col] = cmul(ea, eb);
    } else if (tid == 192) {
        int n = 0;
#pragma unroll
        for (int p = 0; p < 28; p++) {
            if ((amask >> p) & 1u) {
                actL[n++] = p | ((1 << (7 - PI_[p])) << 8)
                              | ((1 << (7 - PJ_[p])) << 16);
            }
        }
        actN_sh = n;
    }
    __syncthreads();                               // sync2: chain start
    const int actN = actN_sh;

    int cp = 0;

    // ---- 3 paired single-qubit steps (H folded) ----
#pragma unroll 1
    for (int g = 0; g < 3; g++) {
        const int ba = 7 - 2 * g, bb = 6 - 2 * g;
        const int ma = 1 << ba, mb = 1 << bb;
        const int row  = (((tid >> ba) & 1) << 1) | ((tid >> bb) & 1);
        const int base = tid & ~(ma | mb);
        const float2* M = &u2s[g][row * 4];
        float2 r = cmul(M[0], buf[cp][base]);
        r = cmad(r, M[1], buf[cp][base | mb]);
        r = cmad(r, M[2], buf[cp][base | ma]);
        r = cmad(r, M[3], buf[cp][base | ma | mb]);
        buf[cp ^ 1][tid] = r;
        __syncthreads();
        cp ^= 1;
    }
    // ---- 4th paired step, ising diagonal folded into the write ----
    {
        const int ma = 2, mb = 1;
        const int row  = (tid & 3);
        const int base = tid & ~3;
        const float2* M = &u2s[3][row * 4];
        float2 r = cmul(M[0], buf[cp][base]);
        r = cmad(r, M[1], buf[cp][base | mb]);
        r = cmad(r, M[2], buf[cp][base | ma]);
        r = cmad(r, M[3], buf[cp][base | ma | mb]);
        buf[cp ^ 1][tid] = cmul(sD[tid], r);
        __syncthreads();
        cp ^= 1;
    }

    // ---- 4 H(x)H steps ----
#pragma unroll 1
    for (int g = 0; g < 4; g++) {
        const int ba = 7 - 2 * g, bb = 6 - 2 * g;
        const int ma = 1 << ba, mb = 1 << bb;
        const int base = tid & ~(ma | mb);
        const float sa = (tid & ma) ? -1.f : 1.f;
        const float sb = (tid & mb) ? -1.f : 1.f;
        const float2 a00 = buf[cp][base];
        const float2 a01 = buf[cp][base | mb];
        const float2 a10 = buf[cp][base | ma];
        const float2 a11 = buf[cp][base | ma | mb];
        float2 r;
        r.x = 0.5f * ((a00.x + sb * a01.x) + sa * (a10.x + sb * a11.x));
        r.y = 0.5f * ((a00.y + sb * a01.y) + sa * (a10.y + sb * a11.y));
        buf[cp ^ 1][tid] = r;
        __syncthreads();
        cp ^= 1;
    }

    // ---- dense conv+pool 4x4 applies ----
#pragma unroll 1
    for (int a = 0; a < actN; a++) {
        const int packed = actL[a];
        const int p  = packed & 255;
        const int mi = (packed >> 8) & 255;
        const int mj = (packed >> 16) & 255;
        const int row  = ((tid & mi) ? 2 : 0) | ((tid & mj) ? 1 : 0);
        const int base = tid & ~(mi | mj);
        const float2* M = &pairM[p][row * 4];
        float2 r = cmul(M[0], buf[cp][base]);
        r = cmad(r, M[1], buf[cp][base | mj]);
        r = cmad(r, M[2], buf[cp][base | mi]);
        r = cmad(r, M[3], buf[cp][base | mi | mj]);
        buf[cp ^ 1][tid] = r;
        __syncthreads();
        cp ^= 1;
    }

    // publish state, then release the workers
    g_psi[tid] = buf[cp][tid];
    __threadfence();
    __syncthreads();
    if (tid == 0 && gridDim.x > 1) g_flag = 1;
}

// fallback for unexpected out_size (planar [Re|Im])
__global__ void __launch_bounds__(256)
outer_planar_kernel(float* __restrict__ out) {
    const int r = blockIdx.x;
    const int c = threadIdx.x;
    const float2 a = g_psi[r];
    const float2 b = g_psi[c];
    out[r * DIM + c]             = a.x * b.x + a.y * b.y;
    out[DIM * DIM + r * DIM + c] = a.y * b.x - a.x * b.y;
}

extern "C" void kernel_launch(void* const* d_in, const int* in_sizes, int n_in,
                              void* d_out, int out_size) {
    const float* x   = nullptr;
    const float* w   = nullptr;
    const float* cpl = nullptr;
    for (int i = 0; i < n_in; i++) {
        if      (in_sizes[i] == 256) x   = (const float*)d_in[i];
        else if (in_sizes[i] == 210) w   = (const float*)d_in[i];
        else if (in_sizes[i] == 64)  cpl = (const float*)d_in[i];
    }

    if (out_size == DIM * DIM) {
        fused_kernel<<<65, 256>>>(x, w, cpl, (float4*)d_out);
    } else {
        fused_kernel<<<1, 256>>>(x, w, cpl, (float4*)d_out);
        outer_planar_kernel<<<DIM, DIM>>>((float*)d_out);
    }
}